// round 1
// baseline (speedup 1.0000x reference)
#include <cuda_runtime.h>

#define HH   8
#define DD   128
#define NEXP 4
#define KSEL 2
#define MAXL 16384
#define MAXS 8

// ---- scratch (device globals; no allocation allowed) ----
__device__ int   g_sel_e[2 * MAXL];
__device__ float g_sel_v[2 * MAXL];
__device__ int   g_rank [2 * MAXL];
__device__ int   g_sample[MAXL];
__device__ int   g_counts[MAXS * NEXP];
__device__ int   g_offs  [MAXS * NEXP + 1];

// ---------------------------------------------------------------------------
// K1: per-token softmax over experts, top-2 selection, mask, sample id
// ---------------------------------------------------------------------------
__global__ void k1_topk(const float* __restrict__ e, const int* __restrict__ cu,
                        int L, int S,
                        float* __restrict__ o_e, float* __restrict__ o_mask)
{
    int t = blockIdx.x * blockDim.x + threadIdx.x;
    if (t >= L) return;

    float x[NEXP];
    float m = -1e30f;
#pragma unroll
    for (int i = 0; i < NEXP; i++) { x[i] = e[(size_t)t * NEXP + i]; m = fmaxf(m, x[i]); }
    float ssum = 0.0f;
#pragma unroll
    for (int i = 0; i < NEXP; i++) { x[i] = expf(x[i] - m); ssum += x[i]; }
    float inv = 1.0f / ssum;
#pragma unroll
    for (int i = 0; i < NEXP; i++) { x[i] *= inv; o_e[(size_t)t * NEXP + i] = x[i]; }

    // top-2 with first-index-wins tie-break (matches lax.top_k)
    int b0 = 0; float v0 = x[0];
#pragma unroll
    for (int i = 1; i < NEXP; i++) if (x[i] > v0) { v0 = x[i]; b0 = i; }
    int b1 = -1; float v1 = -1e30f;
#pragma unroll
    for (int i = 0; i < NEXP; i++) if (i != b0 && x[i] > v1) { v1 = x[i]; b1 = i; }

#pragma unroll
    for (int i = 0; i < NEXP; i++)
        o_mask[(size_t)t * NEXP + i] = (i == b0 || i == b1) ? 1.0f : 0.0f;

    g_sel_e[2 * t]     = b0;  g_sel_v[2 * t]     = v0;
    g_sel_e[2 * t + 1] = b1;  g_sel_v[2 * t + 1] = v1;

    // searchsorted(cu, t, 'right') - 1
    int s = 0;
    while (s + 1 < S && t >= cu[s + 1]) s++;
    g_sample[t] = s;
}

// ---------------------------------------------------------------------------
// K2: one block per (sample, expert). Chunked block scan over tokens of the
// sample, computing the within-bucket rank of each selection + bucket count.
// ---------------------------------------------------------------------------
__global__ void k2_scan(const int* __restrict__ cu)
{
    int s = blockIdx.x / NEXP;
    int e = blockIdx.x % NEXP;
    int start = cu[s], end = cu[s + 1];

    __shared__ int buf[256];
    int carry = 0;

    for (int base = start; base < end; base += 256) {
        int t = base + (int)threadIdx.x;
        int ind = 0, slot = -1;
        if (t < end) {
            if      (g_sel_e[2 * t]     == e) { ind = 1; slot = 2 * t;     }
            else if (g_sel_e[2 * t + 1] == e) { ind = 1; slot = 2 * t + 1; }
        }
        buf[threadIdx.x] = ind;
        __syncthreads();
        // Hillis-Steele inclusive scan
        for (int off = 1; off < 256; off <<= 1) {
            int val = (threadIdx.x >= (unsigned)off) ? buf[threadIdx.x - off] : 0;
            __syncthreads();
            buf[threadIdx.x] += val;
            __syncthreads();
        }
        int incl = buf[threadIdx.x];
        if (slot >= 0) g_rank[slot] = carry + incl - ind;
        carry += buf[255];
        __syncthreads();
    }
    if (threadIdx.x == 0) g_counts[s * NEXP + e] = carry;
}

// ---------------------------------------------------------------------------
// K3: cumsum over S*N bucket counts -> offsets + state_sizes outputs
// ---------------------------------------------------------------------------
__global__ void k3_offsets(int SN, float* __restrict__ o_off, float* __restrict__ o_state)
{
    if (threadIdx.x == 0 && blockIdx.x == 0) {
        int acc = 0;
        g_offs[0] = 0;
        o_off[0] = 0.0f;
        for (int i = 0; i < SN; i++) {
            int c = g_counts[i];
            o_state[i] = (float)c;
            acc += c;
            g_offs[i + 1] = acc;
            o_off[i + 1] = (float)acc;
        }
    }
}

// ---------------------------------------------------------------------------
// K4: one block per token. Reads the token's q/k/v rows ONCE (float4) and
// scatters to both destination rows (slot0, slot1), scaling q/k by the
// routing weights. Also writes gk/beta/global_sorted.
// ---------------------------------------------------------------------------
__global__ void __launch_bounds__(256) k4_scatter(
    const float* __restrict__ q, const float* __restrict__ k, const float* __restrict__ v,
    const float* __restrict__ gk, const float* __restrict__ beta,
    float* __restrict__ o_q, float* __restrict__ o_k, float* __restrict__ o_v,
    float* __restrict__ o_gk, float* __restrict__ o_beta, float* __restrict__ o_gs)
{
    int t = blockIdx.x;
    int s = g_sample[t];
    int e0 = g_sel_e[2 * t], e1 = g_sel_e[2 * t + 1];
    float w0 = g_sel_v[2 * t], w1 = g_sel_v[2 * t + 1];
    long p0 = (long)g_offs[s * NEXP + e0] + g_rank[2 * t];
    long p1 = (long)g_offs[s * NEXP + e1] + g_rank[2 * t + 1];

    const int ROW = HH * DD;              // 1024 floats
    int i = threadIdx.x;                   // 256 float4s per row

    const float4* qs = (const float4*)(q + (size_t)t * ROW);
    const float4* ks = (const float4*)(k + (size_t)t * ROW);
    const float4* vs = (const float4*)(v + (size_t)t * ROW);

    float4* qd0 = (float4*)(o_q + (size_t)p0 * ROW);
    float4* qd1 = (float4*)(o_q + (size_t)p1 * ROW);
    float4* kd0 = (float4*)(o_k + (size_t)p0 * ROW);
    float4* kd1 = (float4*)(o_k + (size_t)p1 * ROW);
    float4* vd0 = (float4*)(o_v + (size_t)p0 * ROW);
    float4* vd1 = (float4*)(o_v + (size_t)p1 * ROW);

    float4 a = qs[i];
    float4 a0 = make_float4(a.x * w0, a.y * w0, a.z * w0, a.w * w0);
    float4 a1 = make_float4(a.x * w1, a.y * w1, a.z * w1, a.w * w1);
    qd0[i] = a0; qd1[i] = a1;

    float4 b = ks[i];
    float4 b0 = make_float4(b.x * w0, b.y * w0, b.z * w0, b.w * w0);
    float4 b1 = make_float4(b.x * w1, b.y * w1, b.z * w1, b.w * w1);
    kd0[i] = b0; kd1[i] = b1;

    float4 c = vs[i];
    vd0[i] = c; vd1[i] = c;

    if (i < HH) {
        float g = gk[(size_t)t * HH + i];
        float bt = beta[(size_t)t * HH + i];
        o_gk[(size_t)p0 * HH + i] = g;
        o_gk[(size_t)p1 * HH + i] = g;
        o_beta[(size_t)p0 * HH + i] = bt;
        o_beta[(size_t)p1 * HH + i] = bt;
    }
    if (i == 0) {
        o_gs[p0] = (float)t;
        o_gs[p1] = (float)t;
    }
}

// ---------------------------------------------------------------------------
extern "C" void kernel_launch(void* const* d_in, const int* in_sizes, int n_in,
                              void* d_out, int out_size)
{
    const float* q    = (const float*)d_in[0];
    const float* k    = (const float*)d_in[1];
    const float* v    = (const float*)d_in[2];
    const float* gk   = (const float*)d_in[3];
    const float* beta = (const float*)d_in[4];
    const float* e    = (const float*)d_in[5];
    const int*   cu   = (const int*)d_in[6];

    int L = in_sizes[0] / (HH * DD);
    int S = in_sizes[6] - 1;

    float* out = (float*)d_out;
    size_t LKHD = (size_t)L * KSEL * HH * DD;
    float* o_q     = out;
    float* o_k     = o_q + LKHD;
    float* o_v     = o_k + LKHD;
    float* o_gk    = o_v + LKHD;
    float* o_beta  = o_gk + (size_t)L * KSEL * HH;
    float* o_e     = o_beta + (size_t)L * KSEL * HH;
    float* o_mask  = o_e + (size_t)L * NEXP;
    float* o_off   = o_mask + (size_t)L * NEXP;
    float* o_state = o_off + (size_t)(S * NEXP + 1);
    float* o_gs    = o_state + (size_t)(S * NEXP);

    k1_topk<<<(L + 255) / 256, 256>>>(e, cu, L, S, o_e, o_mask);
    k2_scan<<<S * NEXP, 256>>>(cu);
    k3_offsets<<<1, 32>>>(S * NEXP, o_off, o_state);
    k4_scatter<<<L, 256>>>(q, k, v, gk, beta, o_q, o_k, o_v, o_gk, o_beta, o_gs);
}

// round 2
// speedup vs baseline: 1.0875x; 1.0875x over previous
#include <cuda_runtime.h>

#define HH   8
#define DD   128
#define NEXP 4
#define KSEL 2
#define MAXL 16384
#define MAXS 8

// ---- scratch (device globals; no allocation allowed) ----
__device__ int   g_sel_e[2 * MAXL];
__device__ float g_sel_v[2 * MAXL];
__device__ int   g_rank [2 * MAXL];
__device__ int   g_sample[MAXL];
__device__ int   g_counts[MAXS * NEXP];
__device__ int   g_offs  [MAXS * NEXP + 1];
__device__ int   g_done;            // zero-initialized; self-resets each run

// ---------------------------------------------------------------------------
// K1: per-token softmax over experts, top-2 selection, mask, sample id
// ---------------------------------------------------------------------------
__global__ void k1_topk(const float* __restrict__ e, const int* __restrict__ cu,
                        int L, int S,
                        float* __restrict__ o_e, float* __restrict__ o_mask)
{
    int t = blockIdx.x * blockDim.x + threadIdx.x;
    if (t >= L) return;

    float x[NEXP];
    float m = -1e30f;
#pragma unroll
    for (int i = 0; i < NEXP; i++) { x[i] = e[(size_t)t * NEXP + i]; m = fmaxf(m, x[i]); }
    float ssum = 0.0f;
#pragma unroll
    for (int i = 0; i < NEXP; i++) { x[i] = expf(x[i] - m); ssum += x[i]; }
    float inv = 1.0f / ssum;
#pragma unroll
    for (int i = 0; i < NEXP; i++) { x[i] *= inv; o_e[(size_t)t * NEXP + i] = x[i]; }

    // top-2 with first-index-wins tie-break (matches lax.top_k)
    int b0 = 0; float v0 = x[0];
#pragma unroll
    for (int i = 1; i < NEXP; i++) if (x[i] > v0) { v0 = x[i]; b0 = i; }
    int b1 = -1; float v1 = -1e30f;
#pragma unroll
    for (int i = 0; i < NEXP; i++) if (i != b0 && x[i] > v1) { v1 = x[i]; b1 = i; }

#pragma unroll
    for (int i = 0; i < NEXP; i++)
        o_mask[(size_t)t * NEXP + i] = (i == b0 || i == b1) ? 1.0f : 0.0f;

    g_sel_e[2 * t]     = b0;  g_sel_v[2 * t]     = v0;
    g_sel_e[2 * t + 1] = b1;  g_sel_v[2 * t + 1] = v1;

    // searchsorted(cu, t, 'right') - 1
    int s = 0;
    while (s + 1 < S && t >= cu[s + 1]) s++;
    g_sample[t] = s;
}

// ---------------------------------------------------------------------------
// K2: one block per (sample, expert), 1024 threads. Ballot/popc-based block
// scan of the 0/1 indicator -> within-bucket ranks + bucket counts.
// Last block to finish performs the cumsum (fused K3) and writes
// offsets/state_sizes. g_done self-resets for graph replay.
// ---------------------------------------------------------------------------
__global__ void __launch_bounds__(1024) k2_scan(
    const int* __restrict__ cu, int SN,
    float* __restrict__ o_off, float* __restrict__ o_state)
{
    int s = blockIdx.x / NEXP;
    int e = blockIdx.x % NEXP;
    int start = cu[s], end = cu[s + 1];

    int tid  = threadIdx.x;
    int lane = tid & 31;
    int warp = tid >> 5;
    int nwarp = blockDim.x >> 5;           // 32
    unsigned lmask_lt = (1u << lane) - 1u;

    __shared__ int wsum[32];
    int carry = 0;

    for (int base = start; base < end; base += blockDim.x) {
        int t = base + tid;
        int ind = 0, slot = -1;
        if (t < end) {
            if      (g_sel_e[2 * t]     == e) { ind = 1; slot = 2 * t;     }
            else if (g_sel_e[2 * t + 1] == e) { ind = 1; slot = 2 * t + 1; }
        }
        unsigned bal = __ballot_sync(0xffffffffu, ind);
        if (lane == 0) wsum[warp] = __popc(bal);
        __syncthreads();
        if (warp == 0) {
            int v = wsum[lane];
#pragma unroll
            for (int off = 1; off < 32; off <<= 1) {
                int y = __shfl_up_sync(0xffffffffu, v, off);
                if (lane >= off) v += y;
            }
            wsum[lane] = v;                 // inclusive warp-sum scan
        }
        __syncthreads();
        int wexcl = warp ? wsum[warp - 1] : 0;
        if (slot >= 0)
            g_rank[slot] = carry + wexcl + __popc(bal & lmask_lt);
        carry += wsum[nwarp - 1];
        __syncthreads();
    }

    if (tid == 0) {
        g_counts[blockIdx.x] = carry;
        __threadfence();
        int old = atomicAdd(&g_done, 1);
        if (old == gridDim.x - 1) {
            g_done = 0;                     // reset for next graph replay
            int acc = 0;
            g_offs[0] = 0;
            o_off[0] = 0.0f;
            for (int i = 0; i < SN; i++) {
                int c = g_counts[i];
                o_state[i] = (float)c;
                acc += c;
                g_offs[i + 1] = acc;
                o_off[i + 1] = (float)acc;
            }
        }
    }
}

// ---------------------------------------------------------------------------
// K4: one block per token. Reads the token's q/k/v rows ONCE (streaming
// float4 loads) and scatters to both destination rows with streaming stores,
// scaling q/k by routing weights. Also writes gk/beta/global_sorted.
// ---------------------------------------------------------------------------
__global__ void __launch_bounds__(256) k4_scatter(
    const float* __restrict__ q, const float* __restrict__ k, const float* __restrict__ v,
    const float* __restrict__ gk, const float* __restrict__ beta,
    float* __restrict__ o_q, float* __restrict__ o_k, float* __restrict__ o_v,
    float* __restrict__ o_gk, float* __restrict__ o_beta, float* __restrict__ o_gs)
{
    int t = blockIdx.x;
    int s = g_sample[t];
    int e0 = g_sel_e[2 * t], e1 = g_sel_e[2 * t + 1];
    float w0 = g_sel_v[2 * t], w1 = g_sel_v[2 * t + 1];
    long p0 = (long)g_offs[s * NEXP + e0] + g_rank[2 * t];
    long p1 = (long)g_offs[s * NEXP + e1] + g_rank[2 * t + 1];

    const int ROW = HH * DD;               // 1024 floats = 256 float4
    int i = threadIdx.x;

    const float4* qs = (const float4*)(q + (size_t)t * ROW);
    const float4* ks = (const float4*)(k + (size_t)t * ROW);
    const float4* vs = (const float4*)(v + (size_t)t * ROW);

    float4* qd0 = (float4*)(o_q + (size_t)p0 * ROW);
    float4* qd1 = (float4*)(o_q + (size_t)p1 * ROW);
    float4* kd0 = (float4*)(o_k + (size_t)p0 * ROW);
    float4* kd1 = (float4*)(o_k + (size_t)p1 * ROW);
    float4* vd0 = (float4*)(o_v + (size_t)p0 * ROW);
    float4* vd1 = (float4*)(o_v + (size_t)p1 * ROW);

    float4 a = __ldcs(qs + i);
    float4 b = __ldcs(ks + i);
    float4 c = __ldcs(vs + i);

    __stcs(qd0 + i, make_float4(a.x * w0, a.y * w0, a.z * w0, a.w * w0));
    __stcs(qd1 + i, make_float4(a.x * w1, a.y * w1, a.z * w1, a.w * w1));
    __stcs(kd0 + i, make_float4(b.x * w0, b.y * w0, b.z * w0, b.w * w0));
    __stcs(kd1 + i, make_float4(b.x * w1, b.y * w1, b.z * w1, b.w * w1));
    __stcs(vd0 + i, c);
    __stcs(vd1 + i, c);

    if (i < HH) {
        float g  = gk[(size_t)t * HH + i];
        float bt = beta[(size_t)t * HH + i];
        o_gk[(size_t)p0 * HH + i]   = g;
        o_gk[(size_t)p1 * HH + i]   = g;
        o_beta[(size_t)p0 * HH + i] = bt;
        o_beta[(size_t)p1 * HH + i] = bt;
    }
    if (i == 0) {
        o_gs[p0] = (float)t;
        o_gs[p1] = (float)t;
    }
}

// ---------------------------------------------------------------------------
extern "C" void kernel_launch(void* const* d_in, const int* in_sizes, int n_in,
                              void* d_out, int out_size)
{
    const float* q    = (const float*)d_in[0];
    const float* k    = (const float*)d_in[1];
    const float* v    = (const float*)d_in[2];
    const float* gk   = (const float*)d_in[3];
    const float* beta = (const float*)d_in[4];
    const float* e    = (const float*)d_in[5];
    const int*   cu   = (const int*)d_in[6];

    int L = in_sizes[0] / (HH * DD);
    int S = in_sizes[6] - 1;

    float* out = (float*)d_out;
    size_t LKHD = (size_t)L * KSEL * HH * DD;
    float* o_q     = out;
    float* o_k     = o_q + LKHD;
    float* o_v     = o_k + LKHD;
    float* o_gk    = o_v + LKHD;
    float* o_beta  = o_gk + (size_t)L * KSEL * HH;
    float* o_e     = o_beta + (size_t)L * KSEL * HH;
    float* o_mask  = o_e + (size_t)L * NEXP;
    float* o_off   = o_mask + (size_t)L * NEXP;
    float* o_state = o_off + (size_t)(S * NEXP + 1);
    float* o_gs    = o_state + (size_t)(S * NEXP);

    k1_topk<<<(L + 255) / 256, 256>>>(e, cu, L, S, o_e, o_mask);
    k2_scan<<<S * NEXP, 1024>>>(cu, S * NEXP, o_off, o_state);
    k4_scatter<<<L, 256>>>(q, k, v, gk, beta, o_q, o_k, o_v, o_gk, o_beta, o_gs);
}